// round 1
// baseline (speedup 1.0000x reference)
#include <cuda_runtime.h>

// HBilinearUpsample: Poincare-ball geodesic bilinear upsample.
// Key identity: with c=1, geodesic_midpoint(x,y) = P*x + Q*y where (P,Q)
// depend only on the Gram scalars (|x|^2, |y|^2, <x,y>), and
// tanh(atanh(z)/2) = z/(1+sqrt(1-z^2))  -> no transcendentals at all.
// The odd/odd "center" output is a 4-term linear combo of the cell corners
// with coefficients from the cell's Gram matrix.

static constexpr int B  = 8;
static constexpr int C  = 64;
static constexpr int H  = 128;
static constexpr int W  = 128;
static constexpr int HW = H * W;
static constexpr int CHW = C * HW;
static constexpr int Ho = 2 * H;
static constexpr int Wo = 2 * W;

#define EPS_F  1e-15f
#define MAXA_F 0.99999f   // 1 - 1e-5

// Scratch: per-cell Gram scalars (5 fields x B*H*W floats = 2.6 MB total)
__device__ float g_n [B * HW];  // <x00,x00>
__device__ float g_dh[B * HW];  // <x00,x10>  (horizontal)
__device__ float g_dv[B * HW];  // <x00,x01>  (vertical)
__device__ float g_dg[B * HW];  // <x00,x11>  (diagonal)
__device__ float g_da[B * HW];  // <x10,x01>  (anti-diagonal)

// ---------------------------------------------------------------------------
// Kernel 1: Gram scalars. One thread per input cell (b,h,w); reduce over C.
// Neighbor indices are clamped so boundary cells degenerate consistently.
// ---------------------------------------------------------------------------
__global__ void __launch_bounds__(128) gram_kernel(const float* __restrict__ x) {
    const int w = threadIdx.x;
    const int h = blockIdx.x;
    const int b = blockIdx.y;
    const int w1 = min(w + 1, W - 1);
    const int h1 = min(h + 1, H - 1);

    const float* p00 = x + b * CHW + h  * W + w;
    const float* p10 = x + b * CHW + h  * W + w1;
    const float* p01 = x + b * CHW + h1 * W + w;
    const float* p11 = x + b * CHW + h1 * W + w1;

    float n = 0.f, dh = 0.f, dv = 0.f, dg = 0.f, da = 0.f;
#pragma unroll 8
    for (int c = 0; c < C; c++) {
        const int o = c * HW;
        float a00 = p00[o];
        float a10 = p10[o];
        float a01 = p01[o];
        float a11 = p11[o];
        n  = fmaf(a00, a00, n);
        dh = fmaf(a00, a10, dh);
        dv = fmaf(a00, a01, dv);
        dg = fmaf(a00, a11, dg);
        da = fmaf(a10, a01, da);
    }
    const int idx = (b * H + h) * W + w;
    g_n [idx] = n;
    g_dh[idx] = dh;
    g_dv[idx] = dv;
    g_dg[idx] = dg;
    g_da[idx] = da;
}

// ---------------------------------------------------------------------------
// midpoint(x,y) = P*x + Q*y given (|x|^2, |y|^2, <x,y>), c = 1.
// Mirrors the reference clip chain (den clip, wn clip at EPS, atanh clip).
// ---------------------------------------------------------------------------
__device__ __forceinline__ void mid_coeffs(float x2, float y2, float xy,
                                           float& P, float& Q) {
    // w = mobius_add(-x, y) = A*x + B*y
    float den1 = fmaxf(1.f - 2.f * xy + x2 * y2, EPS_F);
    float inv1 = __fdividef(1.f, den1);
    float A = -(1.f - 2.f * xy + y2) * inv1;
    float Bc = (1.f - x2) * inv1;
    // |w|^2 via Gram
    float w2 = A * A * x2 + 2.f * A * Bc * xy + Bc * Bc * y2;
    float wn = sqrtf(fmaxf(w2, EPS_F));
    float wc = fminf(wn, MAXA_F);
    // second = tanh(atanh(wc)/2) * w/wn = tau * w,
    //   tanh(atanh(z)/2) = z / (1 + sqrt(1 - z^2))
    float tau = __fdividef(wc, wn * (1.f + sqrtf(fmaxf(1.f - wc * wc, 0.f))));
    float Sa = tau * A;
    float Sb = tau * Bc;
    // result = mobius_add(x, s), s = Sa*x + Sb*y
    float xs = tau * (A * x2 + Bc * xy);
    float s2 = tau * tau * w2;
    float k = 1.f + 2.f * xs + s2;
    float den2 = fmaxf(1.f + 2.f * xs + x2 * s2, EPS_F);
    float inv2 = __fdividef(1.f, den2);
    P = (k + (1.f - x2) * Sa) * inv2;
    Q = (1.f - x2) * Sb * inv2;
}

// ---------------------------------------------------------------------------
// Kernel 2: one thread per input cell -> 2x2 output quad across all 64 channels.
//   out(2h  ,2w) = x00                      out(2h  ,2w+1) = Pa*x00+Qa*x10
//   out(2h+1,2w) = Pv*x00+Qv*x01            out(2h+1,2w+1) = 4-term center
// Boundary rows/cols are exact copies via clamped neighbors (coeffs sum to 1).
// ---------------------------------------------------------------------------
__global__ void __launch_bounds__(128) upsample_kernel(const float* __restrict__ x,
                                                       float* __restrict__ out) {
    const int w = threadIdx.x;
    const int h = blockIdx.x;
    const int b = blockIdx.y;
    const int w1 = min(w + 1, W - 1);
    const int h1 = min(h + 1, H - 1);

    const int base = b * HW;
    const int i00 = base + h  * W + w;
    const int i10 = base + h  * W + w1;
    const int i01 = base + h1 * W + w;

    const float n00 = g_n[i00], n10 = g_n[i10], n01 = g_n[i01];
    const float n11 = g_n[base + h1 * W + w1];
    const float dhT = g_dh[i00], dhB = g_dh[i01];
    const float dvL = g_dv[i00], dvR = g_dv[i10];
    const float dgd = g_dg[i00], dad = g_da[i00];

    float Pa, Qa, Pv, Qv, Pb, Qb, Pc, Qc;
    mid_coeffs(n00, n10, dhT, Pa, Qa);   // a = mid(x00, x10)  (also out even-row odd-col)
    mid_coeffs(n00, n01, dvL, Pv, Qv);   // mid_v
    mid_coeffs(n01, n11, dhB, Pb, Qb);   // b = mid(x01, x11)

    // Gram of (a, b)
    float a2 = Pa * Pa * n00 + 2.f * Pa * Qa * dhT + Qa * Qa * n10;
    float b2 = Pb * Pb * n01 + 2.f * Pb * Qb * dhB + Qb * Qb * n11;
    float ab = Pa * Pb * dvL + Pa * Qb * dgd + Qa * Pb * dad + Qa * Qb * dvR;
    mid_coeffs(a2, b2, ab, Pc, Qc);      // center = mid(a, b)

    const float C00 = Pc * Pa, C10 = Pc * Qa, C01 = Qc * Pb, C11 = Qc * Qb;

    const float* px = x + b * CHW;
    float* po = out + (size_t)b * C * Ho * Wo;
    const int r0 = 2 * h * Wo + 2 * w;
    const int r1 = r0 + Wo;
    const int o00 = h * W + w, o10 = h * W + w1, o01 = h1 * W + w, o11 = h1 * W + w1;

#pragma unroll 4
    for (int c = 0; c < C; c++) {
        const int o = c * HW;
        float a00 = px[o + o00];
        float a10 = px[o + o10];
        float a01 = px[o + o01];
        float a11 = px[o + o11];

        float2 top, bot;
        top.x = a00;
        top.y = Pa * a00 + Qa * a10;
        bot.x = Pv * a00 + Qv * a01;
        bot.y = C00 * a00 + C10 * a10 + C01 * a01 + C11 * a11;

        const int oo = c * Ho * Wo;
        *reinterpret_cast<float2*>(po + oo + r0) = top;
        *reinterpret_cast<float2*>(po + oo + r1) = bot;
    }
}

extern "C" void kernel_launch(void* const* d_in, const int* in_sizes, int n_in,
                              void* d_out, int out_size) {
    const float* x = (const float*)d_in[0];
    float* out = (float*)d_out;
    (void)in_sizes; (void)n_in; (void)out_size;

    dim3 grid(H, B);
    gram_kernel<<<grid, 128>>>(x);
    upsample_kernel<<<grid, 128>>>(x, out);
}

// round 2
// speedup vs baseline: 1.1815x; 1.1815x over previous
#include <cuda_runtime.h>

// HBilinearUpsample: Poincare-ball geodesic bilinear upsample (c = 1).
// midpoint(x,y) = P*x + Q*y with (P,Q) from Gram scalars only;
// tanh(atanh(z)/2) = z/(1+sqrt(1-z^2)) -> no transcendentals.
//
// 3-kernel pipeline, all with >=4096-block grids for occupancy:
//   K1a gram partials (channel-split x4) -> gp_*[z][cell]
//   K1b per-cell coefficient kernel      -> cf_*[cell]   (8 coeffs)
//   K2  streaming writer (channel-split x4): out quad = linear combo

static constexpr int B  = 8;
static constexpr int C  = 64;
static constexpr int H  = 128;
static constexpr int W  = 128;
static constexpr int HW = H * W;
static constexpr int CHW = C * HW;
static constexpr int Ho = 2 * H;
static constexpr int Wo = 2 * W;
static constexpr int NCELL = B * HW;

static constexpr int ZC  = 4;        // channel split for gram kernel
static constexpr int CPZ = C / ZC;   // 16
static constexpr int ZK  = 4;        // channel split for writer kernel
static constexpr int CPK = C / ZK;   // 16

#define EPS_F  1e-15f
#define MAXA_F 0.99999f   // 1 - 1e-5

// Gram partials: 5 fields x ZC x NCELL floats = 10.5 MB
__device__ float gp_n [ZC][NCELL];
__device__ float gp_dh[ZC][NCELL];
__device__ float gp_dv[ZC][NCELL];
__device__ float gp_dg[ZC][NCELL];
__device__ float gp_da[ZC][NCELL];

// Per-cell combination coefficients: 8 x NCELL floats = 4.2 MB
__device__ float cf_Pa [NCELL];
__device__ float cf_Qa [NCELL];
__device__ float cf_Pv [NCELL];
__device__ float cf_Qv [NCELL];
__device__ float cf_C00[NCELL];
__device__ float cf_C10[NCELL];
__device__ float cf_C01[NCELL];
__device__ float cf_C11[NCELL];

// ---------------------------------------------------------------------------
// K1a: Gram partial sums over a 16-channel slice. Thread per cell (w), grid
// (H, B, ZC). Neighbor indices clamped (boundary degenerates to copy).
// ---------------------------------------------------------------------------
__global__ void __launch_bounds__(128) gram_kernel(const float* __restrict__ x) {
    const int w = threadIdx.x;
    const int h = blockIdx.x;
    const int b = blockIdx.y;
    const int z = blockIdx.z;
    const int w1 = min(w + 1, W - 1);
    const int h1 = min(h + 1, H - 1);

    const float* p00 = x + b * CHW + z * CPZ * HW + h  * W + w;
    const float* p10 = x + b * CHW + z * CPZ * HW + h  * W + w1;
    const float* p01 = x + b * CHW + z * CPZ * HW + h1 * W + w;
    const float* p11 = x + b * CHW + z * CPZ * HW + h1 * W + w1;

    float n = 0.f, dh = 0.f, dv = 0.f, dg = 0.f, da = 0.f;
#pragma unroll
    for (int c = 0; c < CPZ; c++) {
        const int o = c * HW;
        float a00 = p00[o];
        float a10 = p10[o];
        float a01 = p01[o];
        float a11 = p11[o];
        n  = fmaf(a00, a00, n);
        dh = fmaf(a00, a10, dh);
        dv = fmaf(a00, a01, dv);
        dg = fmaf(a00, a11, dg);
        da = fmaf(a10, a01, da);
    }
    const int idx = (b * H + h) * W + w;
    gp_n [z][idx] = n;
    gp_dh[z][idx] = dh;
    gp_dv[z][idx] = dv;
    gp_dg[z][idx] = dg;
    gp_da[z][idx] = da;
}

// ---------------------------------------------------------------------------
// midpoint(x,y) = P*x + Q*y given (|x|^2, |y|^2, <x,y>), c = 1.
// Mirrors the reference clip chain.
// ---------------------------------------------------------------------------
__device__ __forceinline__ void mid_coeffs(float x2, float y2, float xy,
                                           float& P, float& Q) {
    float den1 = fmaxf(1.f - 2.f * xy + x2 * y2, EPS_F);
    float inv1 = __fdividef(1.f, den1);
    float A  = -(1.f - 2.f * xy + y2) * inv1;
    float Bc = (1.f - x2) * inv1;
    float w2 = A * A * x2 + 2.f * A * Bc * xy + Bc * Bc * y2;
    float wn = sqrtf(fmaxf(w2, EPS_F));
    float wc = fminf(wn, MAXA_F);
    float tau = __fdividef(wc, wn * (1.f + sqrtf(fmaxf(1.f - wc * wc, 0.f))));
    float Sa = tau * A;
    float Sb = tau * Bc;
    float xs = tau * (A * x2 + Bc * xy);
    float s2 = tau * tau * w2;
    float k = 1.f + 2.f * xs + s2;
    float den2 = fmaxf(1.f + 2.f * xs + x2 * s2, EPS_F);
    float inv2 = __fdividef(1.f, den2);
    P = (k + (1.f - x2) * Sa) * inv2;
    Q = (1.f - x2) * Sb * inv2;
}

__device__ __forceinline__ float gsum_n (int i) { return (gp_n [0][i] + gp_n [1][i]) + (gp_n [2][i] + gp_n [3][i]); }
__device__ __forceinline__ float gsum_dh(int i) { return (gp_dh[0][i] + gp_dh[1][i]) + (gp_dh[2][i] + gp_dh[3][i]); }
__device__ __forceinline__ float gsum_dv(int i) { return (gp_dv[0][i] + gp_dv[1][i]) + (gp_dv[2][i] + gp_dv[3][i]); }
__device__ __forceinline__ float gsum_dg(int i) { return (gp_dg[0][i] + gp_dg[1][i]) + (gp_dg[2][i] + gp_dg[3][i]); }
__device__ __forceinline__ float gsum_da(int i) { return (gp_da[0][i] + gp_da[1][i]) + (gp_da[2][i] + gp_da[3][i]); }

// ---------------------------------------------------------------------------
// K1b: per-cell coefficients. Thread per cell, grid (H, B).
// ---------------------------------------------------------------------------
__global__ void __launch_bounds__(128) coeff_kernel() {
    const int w = threadIdx.x;
    const int h = blockIdx.x;
    const int b = blockIdx.y;
    const int w1 = min(w + 1, W - 1);
    const int h1 = min(h + 1, H - 1);

    const int base = b * HW;
    const int i00 = base + h  * W + w;
    const int i10 = base + h  * W + w1;
    const int i01 = base + h1 * W + w;
    const int i11 = base + h1 * W + w1;

    const float n00 = gsum_n(i00), n10 = gsum_n(i10);
    const float n01 = gsum_n(i01), n11 = gsum_n(i11);
    const float dhT = gsum_dh(i00), dhB = gsum_dh(i01);
    const float dvL = gsum_dv(i00), dvR = gsum_dv(i10);
    const float dgd = gsum_dg(i00), dad = gsum_da(i00);

    float Pa, Qa, Pv, Qv, Pb, Qb, Pc, Qc;
    mid_coeffs(n00, n10, dhT, Pa, Qa);   // a = mid(x00, x10)
    mid_coeffs(n00, n01, dvL, Pv, Qv);   // mid_v
    mid_coeffs(n01, n11, dhB, Pb, Qb);   // b = mid(x01, x11)

    float a2 = Pa * Pa * n00 + 2.f * Pa * Qa * dhT + Qa * Qa * n10;
    float b2 = Pb * Pb * n01 + 2.f * Pb * Qb * dhB + Qb * Qb * n11;
    float ab = Pa * Pb * dvL + Pa * Qb * dgd + Qa * Pb * dad + Qa * Qb * dvR;
    mid_coeffs(a2, b2, ab, Pc, Qc);      // center = mid(a, b)

    cf_Pa [i00] = Pa;
    cf_Qa [i00] = Qa;
    cf_Pv [i00] = Pv;
    cf_Qv [i00] = Qv;
    cf_C00[i00] = Pc * Pa;
    cf_C10[i00] = Pc * Qa;
    cf_C01[i00] = Qc * Pb;
    cf_C11[i00] = Qc * Qb;
}

// ---------------------------------------------------------------------------
// K2: streaming writer. Thread per cell, grid (H, B, ZK); each z-slice
// handles 16 channels. Pure linear-combination, float2 stores.
// ---------------------------------------------------------------------------
__global__ void __launch_bounds__(128) upsample_kernel(const float* __restrict__ x,
                                                       float* __restrict__ out) {
    const int w = threadIdx.x;
    const int h = blockIdx.x;
    const int b = blockIdx.y;
    const int z = blockIdx.z;
    const int w1 = min(w + 1, W - 1);
    const int h1 = min(h + 1, H - 1);

    const int idx = (b * H + h) * W + w;
    const float Pa  = cf_Pa [idx], Qa  = cf_Qa [idx];
    const float Pv  = cf_Pv [idx], Qv  = cf_Qv [idx];
    const float C00 = cf_C00[idx], C10 = cf_C10[idx];
    const float C01 = cf_C01[idx], C11 = cf_C11[idx];

    const float* px = x + b * CHW + z * CPK * HW;
    float* po = out + (size_t)b * C * Ho * Wo + (size_t)z * CPK * Ho * Wo;
    const int r0 = 2 * h * Wo + 2 * w;
    const int r1 = r0 + Wo;
    const int o00 = h * W + w, o10 = h * W + w1, o01 = h1 * W + w, o11 = h1 * W + w1;

#pragma unroll 4
    for (int c = 0; c < CPK; c++) {
        const int o = c * HW;
        float a00 = px[o + o00];
        float a10 = px[o + o10];
        float a01 = px[o + o01];
        float a11 = px[o + o11];

        float2 top, bot;
        top.x = a00;
        top.y = fmaf(Pa, a00, Qa * a10);
        bot.x = fmaf(Pv, a00, Qv * a01);
        bot.y = fmaf(C00, a00, fmaf(C10, a10, fmaf(C01, a01, C11 * a11)));

        const int oo = c * Ho * Wo;
        *reinterpret_cast<float2*>(po + oo + r0) = top;
        *reinterpret_cast<float2*>(po + oo + r1) = bot;
    }
}

extern "C" void kernel_launch(void* const* d_in, const int* in_sizes, int n_in,
                              void* d_out, int out_size) {
    const float* x = (const float*)d_in[0];
    float* out = (float*)d_out;
    (void)in_sizes; (void)n_in; (void)out_size;

    gram_kernel<<<dim3(H, B, ZC), 128>>>(x);
    coeff_kernel<<<dim3(H, B), 128>>>();
    upsample_kernel<<<dim3(H, B, ZK), 128>>>(x, out);
}

// round 3
// speedup vs baseline: 1.2139x; 1.0274x over previous
#include <cuda_runtime.h>

// HBilinearUpsample: Poincare-ball geodesic bilinear upsample (c = 1).
// midpoint(x,y) = P*x + Q*y with (P,Q) from Gram scalars only;
// tanh(atanh(z)/2) = z/(1+sqrt(1-z^2)) -> no transcendentals.
//
// K1 gram   : float4-vectorized, 8-ch groups/warp, smem-reduced, summed scratch
// K2 coeff  : per-cell 8 combination coefficients (packed [cell][8])
// K3 writer : 2 cells/thread, float2 loads, STG.128 stores

static constexpr int B  = 8;
static constexpr int C  = 64;
static constexpr int H  = 128;
static constexpr int W  = 128;
static constexpr int HW = H * W;
static constexpr int CHW = C * HW;
static constexpr int Ho = 2 * H;
static constexpr int Wo = 2 * W;
static constexpr int HoWo = Ho * Wo;
static constexpr int NCELL = B * HW;

static constexpr int ZK  = 4;        // channel split for writer kernel
static constexpr int CPK = C / ZK;   // 16

#define EPS_F  1e-15f
#define MAXA_F 0.99999f   // 1 - 1e-5

// Summed Gram scalars: fields {n, dh, dv, dg, da} x NCELL = 2.6 MB
__device__ float g_sum[5][NCELL];
// Packed per-cell coefficients {Pa,Qa,Pv,Qv,C00,C10,C01,C11}: 4.2 MB
__device__ float4 cf[NCELL][2];

// ---------------------------------------------------------------------------
// K1: Gram sums. Block (32,8): tx covers W via 4 cells each (float4 loads),
// ty = 8-channel group. Warp-internal shfl provides the w+4 neighbor element.
// smem reduce over ty, then write 5 summed fields. Grid (H, B).
// ---------------------------------------------------------------------------
__global__ void __launch_bounds__(256) gram_kernel(const float* __restrict__ x) {
    const int tx = threadIdx.x;          // 0..31
    const int ty = threadIdx.y;          // 0..7
    const int h  = blockIdx.x;
    const int b  = blockIdx.y;
    const int h1 = min(h + 1, H - 1);

    const float* row0 = x + b * CHW + ty * 8 * HW + h  * W + 4 * tx;
    const float* row1 = x + b * CHW + ty * 8 * HW + h1 * W + 4 * tx;

    float n0=0,n1=0,n2=0,n3=0, dh0=0,dh1=0,dh2=0,dh3=0;
    float dv0=0,dv1=0,dv2=0,dv3=0, dg0=0,dg1=0,dg2=0,dg3=0;
    float da0=0,da1=0,da2=0,da3=0;

#pragma unroll
    for (int c = 0; c < 8; c++) {
        const int o = c * HW;
        float4 v0 = *reinterpret_cast<const float4*>(row0 + o);
        float4 v1 = *reinterpret_cast<const float4*>(row1 + o);
        float e0 = __shfl_down_sync(0xffffffffu, v0.x, 1);
        float e1 = __shfl_down_sync(0xffffffffu, v1.x, 1);
        if (tx == 31) { e0 = v0.w; e1 = v1.w; }  // clamp at w = W-1

        n0  = fmaf(v0.x, v0.x, n0);   n1  = fmaf(v0.y, v0.y, n1);
        n2  = fmaf(v0.z, v0.z, n2);   n3  = fmaf(v0.w, v0.w, n3);
        dh0 = fmaf(v0.x, v0.y, dh0);  dh1 = fmaf(v0.y, v0.z, dh1);
        dh2 = fmaf(v0.z, v0.w, dh2);  dh3 = fmaf(v0.w, e0,   dh3);
        dv0 = fmaf(v0.x, v1.x, dv0);  dv1 = fmaf(v0.y, v1.y, dv1);
        dv2 = fmaf(v0.z, v1.z, dv2);  dv3 = fmaf(v0.w, v1.w, dv3);
        dg0 = fmaf(v0.x, v1.y, dg0);  dg1 = fmaf(v0.y, v1.z, dg1);
        dg2 = fmaf(v0.z, v1.w, dg2);  dg3 = fmaf(v0.w, e1,   dg3);
        da0 = fmaf(v0.y, v1.x, da0);  da1 = fmaf(v0.z, v1.y, da1);
        da2 = fmaf(v0.w, v1.z, da2);  da3 = fmaf(e0,   v1.w, da3);
    }

    // smem layout: red[ty][tx][f*4+j], f in {n,dh,dv,dg,da}
    __shared__ float red[8][32][20];
    float* r = red[ty][tx];
    r[0]=n0;  r[1]=n1;  r[2]=n2;  r[3]=n3;
    r[4]=dh0; r[5]=dh1; r[6]=dh2; r[7]=dh3;
    r[8]=dv0; r[9]=dv1; r[10]=dv2; r[11]=dv3;
    r[12]=dg0; r[13]=dg1; r[14]=dg2; r[15]=dg3;
    r[16]=da0; r[17]=da1; r[18]=da2; r[19]=da3;
    __syncthreads();

    const int tid = ty * 32 + tx;
    const int rowbase = (b * H + h) * W;
#pragma unroll
    for (int k = tid; k < 640; k += 256) {
        const int f = k >> 7;          // field 0..4
        const int w = k & 127;         // cell column
        const int fj = f * 4 + (w & 3);
        const int xw = w >> 2;
        float s = ((red[0][xw][fj] + red[1][xw][fj]) + (red[2][xw][fj] + red[3][xw][fj]))
                + ((red[4][xw][fj] + red[5][xw][fj]) + (red[6][xw][fj] + red[7][xw][fj]));
        g_sum[f][rowbase + w] = s;
    }
}

// ---------------------------------------------------------------------------
// midpoint(x,y) = P*x + Q*y given (|x|^2, |y|^2, <x,y>), c = 1.
// ---------------------------------------------------------------------------
__device__ __forceinline__ void mid_coeffs(float x2, float y2, float xy,
                                           float& P, float& Q) {
    float den1 = fmaxf(1.f - 2.f * xy + x2 * y2, EPS_F);
    float inv1 = __fdividef(1.f, den1);
    float A  = -(1.f - 2.f * xy + y2) * inv1;
    float Bc = (1.f - x2) * inv1;
    float w2 = A * A * x2 + 2.f * A * Bc * xy + Bc * Bc * y2;
    float wn = sqrtf(fmaxf(w2, EPS_F));
    float wc = fminf(wn, MAXA_F);
    float tau = __fdividef(wc, wn * (1.f + sqrtf(fmaxf(1.f - wc * wc, 0.f))));
    float Sa = tau * A;
    float Sb = tau * Bc;
    float xs = tau * (A * x2 + Bc * xy);
    float s2 = tau * tau * w2;
    float k = 1.f + 2.f * xs + s2;
    float den2 = fmaxf(1.f + 2.f * xs + x2 * s2, EPS_F);
    float inv2 = __fdividef(1.f, den2);
    P = (k + (1.f - x2) * Sa) * inv2;
    Q = (1.f - x2) * Sb * inv2;
}

// ---------------------------------------------------------------------------
// K2: per-cell coefficients. Thread per cell, grid (H, B).
// ---------------------------------------------------------------------------
__global__ void __launch_bounds__(128) coeff_kernel() {
    const int w = threadIdx.x;
    const int h = blockIdx.x;
    const int b = blockIdx.y;
    const int w1 = min(w + 1, W - 1);
    const int h1 = min(h + 1, H - 1);

    const int base = b * HW;
    const int i00 = base + h  * W + w;
    const int i10 = base + h  * W + w1;
    const int i01 = base + h1 * W + w;
    const int i11 = base + h1 * W + w1;

    const float n00 = g_sum[0][i00], n10 = g_sum[0][i10];
    const float n01 = g_sum[0][i01], n11 = g_sum[0][i11];
    const float dhT = g_sum[1][i00], dhB = g_sum[1][i01];
    const float dvL = g_sum[2][i00], dvR = g_sum[2][i10];
    const float dgd = g_sum[3][i00], dad = g_sum[4][i00];

    float Pa, Qa, Pv, Qv, Pb, Qb, Pc, Qc;
    mid_coeffs(n00, n10, dhT, Pa, Qa);   // a = mid(x00, x10)
    mid_coeffs(n00, n01, dvL, Pv, Qv);   // mid_v
    mid_coeffs(n01, n11, dhB, Pb, Qb);   // b = mid(x01, x11)

    float a2 = Pa * Pa * n00 + 2.f * Pa * Qa * dhT + Qa * Qa * n10;
    float b2 = Pb * Pb * n01 + 2.f * Pb * Qb * dhB + Qb * Qb * n11;
    float ab = Pa * Pb * dvL + Pa * Qb * dgd + Qa * Pb * dad + Qa * Qb * dvR;
    mid_coeffs(a2, b2, ab, Pc, Qc);      // center = mid(a, b)

    cf[i00][0] = make_float4(Pa, Qa, Pv, Qv);
    cf[i00][1] = make_float4(Pc * Pa, Pc * Qa, Qc * Pb, Qc * Qb);
}

// ---------------------------------------------------------------------------
// K3: writer. Block (64,2): tx handles 2 adjacent cells -> 4 contiguous
// outputs per row -> STG.128. Grid (H/2, B, ZK), 16 channels per z.
// ---------------------------------------------------------------------------
__global__ void __launch_bounds__(128) upsample_kernel(const float* __restrict__ x,
                                                       float* __restrict__ out) {
    const int t = threadIdx.x;                  // 0..63
    const int h = blockIdx.x * 2 + threadIdx.y;
    const int b = blockIdx.y;
    const int z = blockIdx.z;
    const int w0 = 2 * t;
    const int w2 = min(w0 + 2, W - 1);
    const int h1 = min(h + 1, H - 1);

    const int idx0 = (b * H + h) * W + w0;
    const float4 c0a = cf[idx0][0];     // Pa,Qa,Pv,Qv (cell 0)
    const float4 c0b = cf[idx0][1];     // C00,C10,C01,C11
    const float4 c1a = cf[idx0 + 1][0]; // cell 1
    const float4 c1b = cf[idx0 + 1][1];

    const float* px = x + b * CHW + z * CPK * HW;
    float* po = out + (size_t)b * C * HoWo + (size_t)z * CPK * HoWo;
    const int r0 = (2 * h) * Wo + 4 * t;
    const int r1 = r0 + Wo;
    const int q0 = h * W + w0;
    const int q2 = h * W + w2;
    const int s0 = h1 * W + w0;
    const int s2 = h1 * W + w2;

#pragma unroll 4
    for (int c = 0; c < CPK; c++) {
        const int o = c * HW;
        float2 a  = *reinterpret_cast<const float2*>(px + o + q0); // x00_0, x00_1(=x10_0)
        float  e0 = px[o + q2];                                    // x10_1
        float2 cc = *reinterpret_cast<const float2*>(px + o + s0); // x01_0, x01_1(=x11_0)
        float  e1 = px[o + s2];                                    // x11_1

        float4 top, bot;
        top.x = a.x;
        top.y = fmaf(c0a.x, a.x, c0a.y * a.y);
        top.z = a.y;
        top.w = fmaf(c1a.x, a.y, c1a.y * e0);
        bot.x = fmaf(c0a.z, a.x, c0a.w * cc.x);
        bot.y = fmaf(c0b.x, a.x, fmaf(c0b.y, a.y, fmaf(c0b.z, cc.x, c0b.w * cc.y)));
        bot.z = fmaf(c1a.z, a.y, c1a.w * cc.y);
        bot.w = fmaf(c1b.x, a.y, fmaf(c1b.y, e0, fmaf(c1b.z, cc.y, c1b.w * e1)));

        const int oo = c * HoWo;
        *reinterpret_cast<float4*>(po + oo + r0) = top;
        *reinterpret_cast<float4*>(po + oo + r1) = bot;
    }
}

extern "C" void kernel_launch(void* const* d_in, const int* in_sizes, int n_in,
                              void* d_out, int out_size) {
    const float* x = (const float*)d_in[0];
    float* out = (float*)d_out;
    (void)in_sizes; (void)n_in; (void)out_size;

    gram_kernel<<<dim3(H, B), dim3(32, 8)>>>(x);
    coeff_kernel<<<dim3(H, B), 128>>>();
    upsample_kernel<<<dim3(H / 2, B, ZK), dim3(64, 2)>>>(x, out);
}